// round 1
// baseline (speedup 1.0000x reference)
#include <cuda_runtime.h>
#include <math.h>

#define CH      512
#define HEADS   4
#define HD      128
#define GROUPS  32
#define BATCH   16
#define NS      1024          // h*w = 32*32
#define EPSV    1e-5f

#define CHN     (CH*NS)               // 524288
#define QKVSTR  (3*CHN)               // per-batch qkv stride
#define NSNS    (NS*NS)               // 1048576

// -------- scratch (device-global: allocation-free per harness rules) --------
__device__ float g_xn [(size_t)BATCH*CH*NS];          //  32 MB
__device__ float g_qkv[(size_t)BATCH*3*CH*NS];        //  96 MB
__device__ float g_S  [(size_t)BATCH*HEADS*NS*NS];    // 256 MB
__device__ float g_ao [(size_t)BATCH*CH*NS];          //  32 MB

// ---------------------------- GroupNorm -------------------------------------
// one block per (batch, group); group = 16 channels * 1024 spatial = 16384 floats
__global__ void groupnorm_kernel(const float* __restrict__ x,
                                 const float* __restrict__ gamma,
                                 const float* __restrict__ beta,
                                 float* __restrict__ out) {
    const int CPG = CH / GROUPS;      // 16
    const int GSZ = CPG * NS;         // 16384
    int b = blockIdx.x / GROUPS, g = blockIdx.x % GROUPS;
    const float* xp = x   + (size_t)b*CHN + (size_t)g*GSZ;
    float*       op = out + (size_t)b*CHN + (size_t)g*GSZ;

    float s = 0.f, s2 = 0.f;
    for (int i = threadIdx.x; i < GSZ; i += blockDim.x) {
        float v = xp[i]; s += v; s2 += v*v;
    }
    __shared__ float rs[8], rs2[8];
    for (int o = 16; o; o >>= 1) {
        s  += __shfl_xor_sync(0xffffffffu, s,  o);
        s2 += __shfl_xor_sync(0xffffffffu, s2, o);
    }
    int wid = threadIdx.x >> 5, lid = threadIdx.x & 31;
    if (lid == 0) { rs[wid] = s; rs2[wid] = s2; }
    __syncthreads();
    s = 0.f; s2 = 0.f;
    #pragma unroll
    for (int i = 0; i < 8; i++) { s += rs[i]; s2 += rs2[i]; }
    float mu   = s / GSZ;
    float var  = s2 / GSZ - mu*mu;
    float rstd = rsqrtf(var + EPSV);

    for (int i = threadIdx.x; i < GSZ; i += blockDim.x) {
        int c = g*CPG + i / NS;
        op[i] = (xp[i] - mu) * rstd * gamma[c] + beta[c];
    }
}

// ------------------------------ GEMM -----------------------------------------
// C[M,N] = alpha * A·B (+ bias[m]) (+ resid)
// TA: A stored [K,M] (lda = M-stride of k-rows) else [M,K] (lda = K-stride of m-rows)
// TB: B stored [N,K] else [K,N]
// EPI: 0 = alpha only; 1 = + bias[m]; 2 = + bias[m] + resid
// Per-z operand offset = (z/zdiv)*s?1 + (z%zdiv)*s?2
template<bool TA, bool TB, int EPI>
__global__ __launch_bounds__(256)
void gemm_kernel(const float* __restrict__ A, const float* __restrict__ Bg,
                 float* __restrict__ C,
                 int M, int Nn, int K, int lda, int ldb, int ldc,
                 int zdiv,
                 long long sA1, long long sA2,
                 long long sB1, long long sB2,
                 long long sC1, long long sC2,
                 const float* __restrict__ bias,
                 const float* __restrict__ resid, long long sR1,
                 float alpha) {
    const int BM = 64, BN = 64, BK = 16, PAD = 4;
    __shared__ float As[BK][BM + PAD];
    __shared__ float Bs[BK][BN + PAD];

    int z  = blockIdx.z;
    int zi = z / zdiv, zj = z % zdiv;
    const float* Ap = A  + zi*sA1 + zj*sA2;
    const float* Bp = Bg + zi*sB1 + zj*sB2;
    float*       Cp = C  + zi*sC1 + zj*sC2;

    int m0 = blockIdx.y * BM;
    int n0 = blockIdx.x * BN;
    int tid = threadIdx.x;
    int tx = tid & 15, ty = tid >> 4;   // 16x16 threads, 4x4 microtile

    float acc[4][4] = {};

    for (int k0 = 0; k0 < K; k0 += BK) {
        // load A tile -> As[k][m]
        #pragma unroll
        for (int r = 0; r < 4; r++) {
            int i = tid + r*256;
            if (TA) { int k = i >> 6, m = i & 63;
                As[k][m] = Ap[(size_t)(k0+k)*lda + m0 + m];
            } else {  int k = i & 15, m = i >> 4;
                As[k][m] = Ap[(size_t)(m0+m)*lda + k0 + k];
            }
        }
        // load B tile -> Bs[k][n]
        #pragma unroll
        for (int r = 0; r < 4; r++) {
            int i = tid + r*256;
            if (!TB) { int k = i >> 6, n = i & 63;
                Bs[k][n] = Bp[(size_t)(k0+k)*ldb + n0 + n];
            } else {   int k = i & 15, n = i >> 4;
                Bs[k][n] = Bp[(size_t)(n0+n)*ldb + k0 + k];
            }
        }
        __syncthreads();
        #pragma unroll
        for (int k = 0; k < BK; k++) {
            float a[4], bb[4];
            *(float4*)a  = *(const float4*)&As[k][ty*4];
            *(float4*)bb = *(const float4*)&Bs[k][tx*4];
            #pragma unroll
            for (int i = 0; i < 4; i++)
                #pragma unroll
                for (int j = 0; j < 4; j++)
                    acc[i][j] = fmaf(a[i], bb[j], acc[i][j]);
        }
        __syncthreads();
    }

    #pragma unroll
    for (int i = 0; i < 4; i++) {
        int m = m0 + ty*4 + i;
        float bv = (EPI >= 1) ? bias[m] : 0.f;
        float4 v;
        float* vp = &v.x;
        #pragma unroll
        for (int j = 0; j < 4; j++) {
            int n = n0 + tx*4 + j;
            float val = acc[i][j] * alpha + bv;
            if (EPI == 2)
                val += resid[(size_t)z*sR1 + (size_t)m*ldc + n];
            vp[j] = val;
        }
        *(float4*)&Cp[(size_t)m*ldc + n0 + tx*4] = v;
    }
}

// ----------------------------- Softmax ---------------------------------------
// one block (256 threads) per row of length NS=1024; each thread owns a float4
__global__ __launch_bounds__(256)
void softmax_kernel(float* __restrict__ S) {
    float4* row = (float4*)(S + (size_t)blockIdx.x * NS);
    int tid = threadIdx.x;
    float4 v = row[tid];
    __shared__ float red[8];

    float m = fmaxf(fmaxf(v.x, v.y), fmaxf(v.z, v.w));
    for (int o = 16; o; o >>= 1) m = fmaxf(m, __shfl_xor_sync(0xffffffffu, m, o));
    if ((tid & 31) == 0) red[tid >> 5] = m;
    __syncthreads();
    m = red[0];
    #pragma unroll
    for (int i = 1; i < 8; i++) m = fmaxf(m, red[i]);

    v.x = __expf(v.x - m); v.y = __expf(v.y - m);
    v.z = __expf(v.z - m); v.w = __expf(v.w - m);
    float s = v.x + v.y + v.z + v.w;
    for (int o = 16; o; o >>= 1) s += __shfl_xor_sync(0xffffffffu, s, o);
    __syncthreads();
    if ((tid & 31) == 0) red[tid >> 5] = s;
    __syncthreads();
    s = 0.f;
    #pragma unroll
    for (int i = 0; i < 8; i++) s += red[i];

    float inv = 1.0f / s;
    v.x *= inv; v.y *= inv; v.z *= inv; v.w *= inv;
    row[tid] = v;
}

// ------------------------------ launch ----------------------------------------
extern "C" void kernel_launch(void* const* d_in, const int* in_sizes, int n_in,
                              void* d_out, int out_size) {
    const float* x      = (const float*)d_in[0];
    const float* gamma  = (const float*)d_in[1];
    const float* beta   = (const float*)d_in[2];
    const float* w_qkv  = (const float*)d_in[3];
    const float* b_qkv  = (const float*)d_in[4];
    const float* w_proj = (const float*)d_in[5];
    const float* b_proj = (const float*)d_in[6];
    float* out = (float*)d_out;

    float *xn, *qkv, *S, *ao;
    cudaGetSymbolAddress((void**)&xn,  g_xn);
    cudaGetSymbolAddress((void**)&qkv, g_qkv);
    cudaGetSymbolAddress((void**)&S,   g_S);
    cudaGetSymbolAddress((void**)&ao,  g_ao);

    // 1) GroupNorm
    groupnorm_kernel<<<BATCH*GROUPS, 256>>>(x, gamma, beta, xn);

    // 2) QKV: per batch  C[1536,1024] = w_qkv[1536,512] * xn[512,1024] + b_qkv
    gemm_kernel<false,false,1><<<dim3(NS/64, 3*CH/64, BATCH), 256>>>(
        w_qkv, xn, qkv,
        3*CH, NS, CH, CH, NS, NS,
        1, 0, 0, (long long)CHN, 0, (long long)QKVSTR, 0,
        b_qkv, nullptr, 0, 1.0f);

    // 3) S = (q^T k) * hd^-0.5  per (b, head):  M=N=1024, K=128
    const float scale = 0.08838834764831845f;   // 1/sqrt(128)
    gemm_kernel<true,false,0><<<dim3(NS/64, NS/64, BATCH*HEADS), 256>>>(
        qkv, qkv + CHN, S,
        NS, NS, HD, NS, NS, NS,
        HEADS,
        (long long)QKVSTR, (long long)HD*NS,
        (long long)QKVSTR, (long long)HD*NS,
        (long long)HEADS*NSNS, (long long)NSNS,
        nullptr, nullptr, 0, scale);

    // 4) row-wise softmax over 65536 rows of length 1024
    softmax_kernel<<<BATCH*HEADS*NS, 256>>>(S);

    // 5) O = V * P^T  per (b, head):  M=128(c), N=1024(n), K=1024(m)
    gemm_kernel<false,true,0><<<dim3(NS/64, HD/64, BATCH*HEADS), 256>>>(
        qkv + 2*CHN, S, ao,
        HD, NS, NS, NS, NS, NS,
        HEADS,
        (long long)QKVSTR, (long long)HD*NS,
        (long long)HEADS*NSNS, (long long)NSNS,
        (long long)CHN, (long long)HD*NS,
        nullptr, nullptr, 0, 1.0f);

    // 6) out = x + w_proj * ao + b_proj   per batch
    gemm_kernel<false,false,2><<<dim3(NS/64, CH/64, BATCH), 256>>>(
        w_proj, ao, out,
        CH, NS, CH, CH, NS, NS,
        1, 0, 0, (long long)CHN, 0, (long long)CHN, 0,
        b_proj, x, (long long)CHN, 1.0f);
}

// round 3
// speedup vs baseline: 3.1884x; 3.1884x over previous
#include <cuda_runtime.h>
#include <cuda_fp16.h>
#include <cstdint>
#include <math.h>

typedef __half ht;

#define NCH  512
#define NSP  1024
#define NB   16
#define CHN  (NCH*NSP)
#define NSNS (NSP*NSP)
#define QS   0.08838834764831845f

// --------------------------- scratch (device globals) ------------------------
__device__ ht    g_xn [(size_t)NB*NSP*NCH];      // [b][n][c]  B of QKV
__device__ ht    g_wqh[1536*512], g_wql[1536*512];
__device__ ht    g_wph[512*512],  g_wpl[512*512];
__device__ ht    g_qkh[(size_t)NB*NSP*1024];     // [b][n][q0-511|k512-1023]
__device__ ht    g_qkl[(size_t)NB*NSP*1024];
__device__ ht    g_vh [(size_t)NB*NCH*NSP];      // [b][c][m]
__device__ ht    g_vl [(size_t)NB*NCH*NSP];
__device__ float g_S  [(size_t)64*NSNS];         // [b*4+h][n][m]
__device__ ht    g_P  [(size_t)64*NSNS];
__device__ ht    g_oT [(size_t)NB*NSP*NCH];      // [b][n][c]

// ------------------------------ PTX helpers ----------------------------------
__device__ __forceinline__ uint32_t smem_u32(const void* p) {
    uint32_t a;
    asm("{ .reg .u64 t; cvta.to.shared.u64 t, %1; cvt.u32.u64 %0, t; }" : "=r"(a) : "l"(p));
    return a;
}
__device__ __forceinline__ void ldsm4(uint32_t* r, uint32_t addr) {
    asm volatile("ldmatrix.sync.aligned.m8n8.x4.shared.b16 {%0,%1,%2,%3}, [%4];"
        : "=r"(r[0]), "=r"(r[1]), "=r"(r[2]), "=r"(r[3]) : "r"(addr));
}
__device__ __forceinline__ void mma16816(float* d, const uint32_t* a, uint32_t b0, uint32_t b1) {
    asm volatile("mma.sync.aligned.m16n8k16.row.col.f32.f16.f16.f32 "
        "{%0,%1,%2,%3}, {%4,%5,%6,%7}, {%8,%9}, {%0,%1,%2,%3};"
        : "+f"(d[0]), "+f"(d[1]), "+f"(d[2]), "+f"(d[3])
        : "r"(a[0]), "r"(a[1]), "r"(a[2]), "r"(a[3]), "r"(b0), "r"(b1));
}
#define CP_ASYNC(dst, src) asm volatile("cp.async.cg.shared.global [%0], [%1], 16;" :: "r"(dst), "l"(src))
#define CP_COMMIT()  asm volatile("cp.async.commit_group;" ::: "memory")
#define CP_WAIT1()   asm volatile("cp.async.wait_group 1;" ::: "memory")
#define CP_WAIT0()   asm volatile("cp.async.wait_group 0;" ::: "memory")

// --------------------------- weight split kernel -----------------------------
__global__ __launch_bounds__(256)
void convw_kernel(const float* __restrict__ wq, const float* __restrict__ wp,
                  ht* __restrict__ wqh, ht* __restrict__ wql,
                  ht* __restrict__ wph, ht* __restrict__ wpl) {
    int i = blockIdx.x * 256 + threadIdx.x;
    if (i < 1536*512) {
        float v = wq[i];
        if (i < 512*512) v *= QS;                 // fold q-scale into w_q
        ht h = __float2half_rn(v);
        wqh[i] = h; wql[i] = __float2half_rn(v - __half2float(h));
    } else {
        int j = i - 1536*512;
        if (j < 512*512) {
            float v = wp[j];
            ht h = __float2half_rn(v);
            wph[j] = h; wpl[j] = __float2half_rn(v - __half2float(h));
        }
    }
}

// ------------------------------ GroupNorm ------------------------------------
__global__ __launch_bounds__(256)
void groupnorm_kernel(const float* __restrict__ x, const float* __restrict__ gamma,
                      const float* __restrict__ beta, ht* __restrict__ xn) {
    const int b = blockIdx.x >> 5, g = blockIdx.x & 31;
    const float* xp = x + (size_t)b * CHN + (size_t)g * (16 * NSP);

    float s = 0.f, s2 = 0.f;
    for (int i = threadIdx.x; i < 16 * NSP; i += 256) {
        float v = xp[i]; s += v; s2 += v * v;
    }
    __shared__ float rs[8], rs2[8];
    for (int o = 16; o; o >>= 1) {
        s  += __shfl_xor_sync(0xffffffffu, s,  o);
        s2 += __shfl_xor_sync(0xffffffffu, s2, o);
    }
    int wid = threadIdx.x >> 5;
    if ((threadIdx.x & 31) == 0) { rs[wid] = s; rs2[wid] = s2; }
    __syncthreads();
    s = 0.f; s2 = 0.f;
    #pragma unroll
    for (int i = 0; i < 8; i++) { s += rs[i]; s2 += rs2[i]; }
    const float inv = 1.0f / (16 * NSP);
    float mu = s * inv;
    float rstd = rsqrtf(s2 * inv - mu * mu + 1e-5f);

    const int gc = g * 16;
    for (int n = threadIdx.x; n < NSP; n += 256) {
        union { ht h[16]; uint4 u[2]; } H;
        #pragma unroll
        for (int c = 0; c < 16; ++c) {
            float v = (xp[c * NSP + n] - mu) * rstd * gamma[gc + c] + beta[gc + c];
            H.h[c] = __float2half_rn(v);
        }
        uint4* dh = (uint4*)(g_xn + (size_t)b * (NSP * NCH) + (size_t)n * NCH + gc);
        dh[0] = H.u[0]; dh[1] = H.u[1];
    }
}

// ------------------------------ Softmax --------------------------------------
__global__ __launch_bounds__(256)
void softmax_kernel(const float* __restrict__ S, ht* __restrict__ P) {
    const float4* row = (const float4*)(S + (size_t)blockIdx.x * NSP);
    int tid = threadIdx.x;
    float4 v = row[tid];
    __shared__ float red[8];

    float m = fmaxf(fmaxf(v.x, v.y), fmaxf(v.z, v.w));
    for (int o = 16; o; o >>= 1) m = fmaxf(m, __shfl_xor_sync(0xffffffffu, m, o));
    if ((tid & 31) == 0) red[tid >> 5] = m;
    __syncthreads();
    m = red[0];
    #pragma unroll
    for (int i = 1; i < 8; i++) m = fmaxf(m, red[i]);

    v.x = __expf(v.x - m); v.y = __expf(v.y - m);
    v.z = __expf(v.z - m); v.w = __expf(v.w - m);
    float s = v.x + v.y + v.z + v.w;
    for (int o = 16; o; o >>= 1) s += __shfl_xor_sync(0xffffffffu, s, o);
    __syncthreads();
    if ((tid & 31) == 0) red[tid >> 5] = s;
    __syncthreads();
    s = 0.f;
    #pragma unroll
    for (int i = 0; i < 8; i++) s += red[i];
    float inv = 1.0f / s;

    union { ht h[4]; uint2 u; } H;
    H.h[0] = __float2half_rn(v.x * inv); H.h[1] = __float2half_rn(v.y * inv);
    H.h[2] = __float2half_rn(v.z * inv); H.h[3] = __float2half_rn(v.w * inv);
    *(uint2*)(P + (size_t)blockIdx.x * NSP + tid * 4) = H.u;
}

// --------------------------- mma.sync GEMM -----------------------------------
// D[128x128] = (Ah + Al) * B^T  (both operands K-major fp16, 2 passes)
// MODE 0: QKV  (z=b)     M=1536 N=1024 K=512
// MODE 1: S    (z=b*4+h) M=1024 N=1024 K=128  -> fp32 S
// MODE 2: O    (z=b*4+h) M=128  N=1024 K=1024 -> oT fp16 (transposed)
// MODE 3: proj (z=b)     M=512  N=1024 K=512  -> fp32 out (+bias+x)
#define SROW   80          // padded row: 32 halfs + 8 pad = 80 B
#define TILEB  10240       // 128 * 80
#define STAGEB 30720       // 3 tiles
#define SMEMSZ 61440       // 2 stages

template<int MODE>
__global__ __launch_bounds__(256, 2)
void gemm_mma(const ht* __restrict__ Ah, const ht* __restrict__ Al,
              const ht* __restrict__ Bp,
              float* __restrict__ C,
              ht* __restrict__ Oh, ht* __restrict__ Ol,
              ht* __restrict__ Vh, ht* __restrict__ Vl,
              const float* __restrict__ bias, const float* __restrict__ resid) {
    extern __shared__ char smem[];
    const uint32_t sbase = smem_u32(smem);
    const int tid = threadIdx.x, lane = tid & 31, wid = tid >> 5;
    const int wm = wid & 3, wn = wid >> 2;       // 4 warps M, 2 warps N
    const int m_w = wm * 32, n_w = wn * 64;
    const int z = blockIdx.z, m0 = blockIdx.y * 128, n0 = blockIdx.x * 128;

    int lda, ldb, Ktot;
    size_t aoff, boff;
    if (MODE == 0) {
        lda = 512; ldb = 512; Ktot = 512;
        aoff = (size_t)m0 * 512;
        boff = (size_t)z * (NSP * NCH) + (size_t)n0 * 512;
    } else if (MODE == 1) {
        lda = 1024; ldb = 1024; Ktot = 128;
        int b = z >> 2, h = z & 3;
        aoff = (size_t)b * (NSP * 1024) + (size_t)m0 * 1024 + h * 128;
        boff = (size_t)b * (NSP * 1024) + (size_t)n0 * 1024 + 512 + h * 128;
    } else if (MODE == 2) {
        lda = 1024; ldb = 1024; Ktot = 1024;
        int b = z >> 2, h = z & 3;
        aoff = (size_t)b * (NCH * NSP) + (size_t)(h * 128) * NSP;
        boff = (size_t)z * (size_t)NSNS + (size_t)n0 * 1024;
    } else {
        lda = 512; ldb = 512; Ktot = 512;
        aoff = (size_t)m0 * 512;
        boff = (size_t)z * (NSP * NCH) + (size_t)n0 * 512;
    }

    float acc[2][8][4] = {};
    const int NIT = Ktot / 32;

    // chunk map: 1536 16B-chunks/stage, 6 per thread
    int ct[6], cr[6], cc[6];
    #pragma unroll
    for (int i = 0; i < 6; ++i) {
        int c = tid + i * 256;
        ct[i] = c >> 9; cr[i] = (c >> 2) & 127; cc[i] = c & 3;
    }

    auto load_stage = [&](int it, int s) {
        const int k0 = it * 32;
        const uint32_t sb = sbase + s * STAGEB;
        #pragma unroll
        for (int i = 0; i < 6; ++i) {
            const ht* gp;
            if (ct[i] == 0)      gp = Ah + aoff + (size_t)cr[i] * lda + k0 + cc[i] * 8;
            else if (ct[i] == 1) gp = Al + aoff + (size_t)cr[i] * lda + k0 + cc[i] * 8;
            else                 gp = Bp + boff + (size_t)cr[i] * ldb + k0 + cc[i] * 8;
            CP_ASYNC(sb + ct[i] * TILEB + cr[i] * SROW + cc[i] * 16, gp);
        }
        CP_COMMIT();
    };

    load_stage(0, 0);
    for (int it = 0; it < NIT; ++it) {
        const int s = it & 1;
        if (it + 1 < NIT) { load_stage(it + 1, s ^ 1); CP_WAIT1(); }
        else              { CP_WAIT0(); }
        __syncthreads();

        const uint32_t ab = sbase + s * STAGEB;
        const uint32_t rofs = (lane & 15) * SROW + ((lane >> 4) << 4);
        #pragma unroll
        for (int k16 = 0; k16 < 2; ++k16) {
            const uint32_t ko = k16 * 32 + rofs;
            uint32_t bfr[4][4];
            #pragma unroll
            for (int j = 0; j < 4; ++j)
                ldsm4(bfr[j], ab + 2 * TILEB + (n_w + j * 16) * SROW + ko);
            #pragma unroll
            for (int p = 0; p < 2; ++p) {
                uint32_t af[2][4];
                #pragma unroll
                for (int i = 0; i < 2; ++i)
                    ldsm4(af[i], ab + p * TILEB + (m_w + i * 16) * SROW + ko);
                #pragma unroll
                for (int i = 0; i < 2; ++i)
                    #pragma unroll
                    for (int jn = 0; jn < 8; ++jn)
                        mma16816(acc[i][jn], af[i],
                                 bfr[jn >> 1][jn & 1], bfr[jn >> 1][(jn & 1) + 2]);
            }
        }
        __syncthreads();
    }

    // ------------------------------ epilogue ---------------------------------
    const int fr = lane >> 2;            // frag row 0..7
    const int fc = (lane & 3) * 2;       // frag col (even)

    if (MODE == 1 || MODE == 3) {
        #pragma unroll
        for (int i = 0; i < 2; ++i)
            #pragma unroll
            for (int jn = 0; jn < 8; ++jn)
                #pragma unroll
                for (int rh = 0; rh < 2; ++rh) {
                    int row = m0 + m_w + i * 16 + fr + rh * 8;
                    int col = n0 + n_w + jn * 8 + fc;
                    float v0 = acc[i][jn][rh * 2], v1 = acc[i][jn][rh * 2 + 1];
                    if (MODE == 3) {
                        float bv = bias[row];
                        const float2 xv = *(const float2*)(resid + (size_t)z * CHN + (size_t)row * NSP + col);
                        *(float2*)(C + (size_t)z * CHN + (size_t)row * NSP + col) =
                            make_float2(v0 + bv + xv.x, v1 + bv + xv.y);
                    } else {
                        *(float2*)(C + (size_t)z * NSNS + (size_t)row * NSP + col) =
                            make_float2(v0, v1);
                    }
                }
    } else if (MODE == 0 && m0 >= 1024) {
        // V region: direct [b][c][m] hi/lo
        #pragma unroll
        for (int i = 0; i < 2; ++i)
            #pragma unroll
            for (int jn = 0; jn < 8; ++jn)
                #pragma unroll
                for (int rh = 0; rh < 2; ++rh) {
                    int mi = m_w + i * 16 + fr + rh * 8;
                    float bv = bias[m0 + mi];
                    int cc2 = m0 - 1024 + mi;
                    size_t off = (size_t)z * (NCH * NSP) + (size_t)cc2 * NSP + n0 + n_w + jn * 8 + fc;
                    float v0 = acc[i][jn][rh * 2] + bv, v1 = acc[i][jn][rh * 2 + 1] + bv;
                    ht h0 = __float2half_rn(v0), h1 = __float2half_rn(v1);
                    ht l0 = __float2half_rn(v0 - __half2float(h0));
                    ht l1 = __float2half_rn(v1 - __half2float(h1));
                    *(__half2*)(Vh + off) = __halves2half2(h0, h1);
                    *(__half2*)(Vl + off) = __halves2half2(l0, l1);
                }
    } else {
        // transpose path: MODE 0 q/k region (hi/lo), MODE 2 oT (hi only)
        uint32_t* TB = (uint32_t*)smem;       // [64 n][132 m]
        #pragma unroll
        for (int hh = 0; hh < 2; ++hh) {
            __syncthreads();
            if (wn == hh) {
                #pragma unroll
                for (int i = 0; i < 2; ++i)
                    #pragma unroll
                    for (int jn = 0; jn < 8; ++jn)
                        #pragma unroll
                        for (int rh = 0; rh < 2; ++rh) {
                            int mi = m_w + i * 16 + fr + rh * 8;
                            float bv = 0.f;
                            if (MODE == 0) {
                                bv = bias[m0 + mi];
                                if (m0 < 512) bv *= QS;
                            }
                            float v0 = acc[i][jn][rh * 2] + bv;
                            float v1 = acc[i][jn][rh * 2 + 1] + bv;
                            int ncl = jn * 8 + fc;
                            uint32_t p0, p1;
                            if (MODE == 0) {
                                ht h0 = __float2half_rn(v0);
                                ht l0 = __float2half_rn(v0 - __half2float(h0));
                                ht h1 = __float2half_rn(v1);
                                ht l1 = __float2half_rn(v1 - __half2float(h1));
                                p0 = (uint32_t)__half_as_ushort(h0) | ((uint32_t)__half_as_ushort(l0) << 16);
                                p1 = (uint32_t)__half_as_ushort(h1) | ((uint32_t)__half_as_ushort(l1) << 16);
                            } else {
                                p0 = (uint32_t)__half_as_ushort(__float2half_rn(v0));
                                p1 = (uint32_t)__half_as_ushort(__float2half_rn(v1));
                            }
                            TB[ncl * 132 + mi] = p0;
                            TB[(ncl + 1) * 132 + mi] = p1;
                        }
            }
            __syncthreads();
            int rr = tid >> 2, seg = (tid & 3) * 32;
            if (MODE == 0) {
                size_t nco = (size_t)z * (NSP * 1024) + (size_t)(n0 + hh * 64 + rr) * 1024 + m0 + seg;
                #pragma unroll
                for (int q4 = 0; q4 < 4; ++q4) {
                    union { ht h[8]; uint4 u; } H, L;
                    #pragma unroll
                    for (int e = 0; e < 8; ++e) {
                        uint32_t u = TB[rr * 132 + seg + q4 * 8 + e];
                        H.h[e] = __ushort_as_half((unsigned short)(u & 0xffffu));
                        L.h[e] = __ushort_as_half((unsigned short)(u >> 16));
                    }
                    *(uint4*)(Oh + nco + q4 * 8) = H.u;
                    *(uint4*)(Ol + nco + q4 * 8) = L.u;
                }
            } else {
                int b = z >> 2, h = z & 3;
                size_t nco = (size_t)b * (NSP * NCH) + (size_t)(n0 + hh * 64 + rr) * NCH + h * 128 + seg;
                #pragma unroll
                for (int q4 = 0; q4 < 4; ++q4) {
                    union { ht h[8]; uint4 u; } H;
                    #pragma unroll
                    for (int e = 0; e < 8; ++e) {
                        uint32_t u = TB[rr * 132 + seg + q4 * 8 + e];
                        H.h[e] = __ushort_as_half((unsigned short)(u & 0xffffu));
                    }
                    *(uint4*)(Oh + nco + q4 * 8) = H.u;
                }
            }
        }
    }
}

// ------------------------------ launch ---------------------------------------
extern "C" void kernel_launch(void* const* d_in, const int* in_sizes, int n_in,
                              void* d_out, int out_size) {
    const float* x      = (const float*)d_in[0];
    const float* gamma  = (const float*)d_in[1];
    const float* beta   = (const float*)d_in[2];
    const float* w_qkv  = (const float*)d_in[3];
    const float* b_qkv  = (const float*)d_in[4];
    const float* w_proj = (const float*)d_in[5];
    const float* b_proj = (const float*)d_in[6];
    float* out = (float*)d_out;

    ht *xn, *wqh, *wql, *wph, *wpl, *qkh, *qkl, *vh, *vl, *P, *oT;
    float* S;
    cudaGetSymbolAddress((void**)&xn,  g_xn);
    cudaGetSymbolAddress((void**)&wqh, g_wqh); cudaGetSymbolAddress((void**)&wql, g_wql);
    cudaGetSymbolAddress((void**)&wph, g_wph); cudaGetSymbolAddress((void**)&wpl, g_wpl);
    cudaGetSymbolAddress((void**)&qkh, g_qkh); cudaGetSymbolAddress((void**)&qkl, g_qkl);
    cudaGetSymbolAddress((void**)&vh,  g_vh);  cudaGetSymbolAddress((void**)&vl,  g_vl);
    cudaGetSymbolAddress((void**)&S,   g_S);
    cudaGetSymbolAddress((void**)&P,   g_P);
    cudaGetSymbolAddress((void**)&oT,  g_oT);

    cudaFuncSetAttribute(gemm_mma<0>, cudaFuncAttributeMaxDynamicSharedMemorySize, SMEMSZ);
    cudaFuncSetAttribute(gemm_mma<1>, cudaFuncAttributeMaxDynamicSharedMemorySize, SMEMSZ);
    cudaFuncSetAttribute(gemm_mma<2>, cudaFuncAttributeMaxDynamicSharedMemorySize, SMEMSZ);
    cudaFuncSetAttribute(gemm_mma<3>, cudaFuncAttributeMaxDynamicSharedMemorySize, SMEMSZ);

    convw_kernel<<<4096, 256>>>(w_qkv, w_proj, wqh, wql, wph, wpl);
    groupnorm_kernel<<<NB * 32, 256>>>(x, gamma, beta, xn);

    // QKV: q/k -> qkT (hi/lo, transposed), v -> [b][c][m] (hi/lo)
    gemm_mma<0><<<dim3(8, 12, NB), 256, SMEMSZ>>>(
        wqh, wql, xn, nullptr, qkh, qkl, vh, vl, b_qkv, nullptr);
    // S = (q*scale)^T k
    gemm_mma<1><<<dim3(8, 8, 64), 256, SMEMSZ>>>(
        qkh, qkl, qkh, S, nullptr, nullptr, nullptr, nullptr, nullptr, nullptr);
    // softmax -> P fp16
    softmax_kernel<<<64 * NSP, 256>>>(S, P);
    // O = V P^T -> oT
    gemm_mma<2><<<dim3(8, 1, 64), 256, SMEMSZ>>>(
        vh, vl, P, nullptr, oT, nullptr, nullptr, nullptr, nullptr, nullptr);
    // out = x + w_proj O + b_proj
    gemm_mma<3><<<dim3(8, 4, NB), 256, SMEMSZ>>>(
        wph, wpl, oT, out, nullptr, nullptr, nullptr, nullptr, b_proj, x);
}

// round 4
// speedup vs baseline: 4.6846x; 1.4692x over previous
#include <cuda_runtime.h>
#include <cuda_fp16.h>
#include <cstdint>
#include <math.h>

typedef __half ht;

#define NCH  512
#define NSP  1024
#define NB   16
#define CHN  (NCH*NSP)
#define NSNS (NSP*NSP)
#define QS   0.08838834764831845f

// --------------------------- scratch (device globals) ------------------------
__device__ ht    g_xn [(size_t)NB*NSP*NCH];      // [b][n][c]
__device__ ht    g_wq [1536*512];
__device__ ht    g_wp [512*512];
__device__ ht    g_qk [(size_t)NB*NSP*1024];     // [b][n][q0-511|k512-1023]
__device__ ht    g_v  [(size_t)NB*NCH*NSP];      // [b][c][m]
__device__ float g_S  [(size_t)64*NSNS];         // [b*4+h][n][m]
__device__ ht    g_P  [(size_t)64*NSNS];
__device__ ht    g_oT [(size_t)NB*NSP*NCH];      // [b][n][c]

// ------------------------------ PTX helpers ----------------------------------
__device__ __forceinline__ uint32_t smem_u32(const void* p) {
    uint32_t a;
    asm("{ .reg .u64 t; cvta.to.shared.u64 t, %1; cvt.u32.u64 %0, t; }" : "=r"(a) : "l"(p));
    return a;
}
__device__ __forceinline__ void ldsm4(uint32_t* r, uint32_t addr) {
    asm volatile("ldmatrix.sync.aligned.m8n8.x4.shared.b16 {%0,%1,%2,%3}, [%4];"
        : "=r"(r[0]), "=r"(r[1]), "=r"(r[2]), "=r"(r[3]) : "r"(addr));
}
__device__ __forceinline__ void mma16816(float* d, const uint32_t* a, uint32_t b0, uint32_t b1) {
    asm volatile("mma.sync.aligned.m16n8k16.row.col.f32.f16.f16.f32 "
        "{%0,%1,%2,%3}, {%4,%5,%6,%7}, {%8,%9}, {%0,%1,%2,%3};"
        : "+f"(d[0]), "+f"(d[1]), "+f"(d[2]), "+f"(d[3])
        : "r"(a[0]), "r"(a[1]), "r"(a[2]), "r"(a[3]), "r"(b0), "r"(b1));
}
#define CP_ASYNC(dst, src) asm volatile("cp.async.cg.shared.global [%0], [%1], 16;" :: "r"(dst), "l"(src))
#define CP_COMMIT()  asm volatile("cp.async.commit_group;" ::: "memory")
#define CP_WAIT3()   asm volatile("cp.async.wait_group 3;" ::: "memory")
#define CP_WAIT0()   asm volatile("cp.async.wait_group 0;" ::: "memory")

// --------------------------- weight convert ----------------------------------
__global__ __launch_bounds__(256)
void convw_kernel(const float* __restrict__ wq, const float* __restrict__ wp,
                  ht* __restrict__ wqo, ht* __restrict__ wpo) {
    int i = blockIdx.x * 256 + threadIdx.x;
    if (i < 1536*512) {
        float v = wq[i];
        if (i < 512*512) v *= QS;                 // fold q-scale into w_q
        wqo[i] = __float2half_rn(v);
    } else {
        int j = i - 1536*512;
        if (j < 512*512) wpo[j] = __float2half_rn(wp[j]);
    }
}

// ------------------------------ GroupNorm ------------------------------------
__global__ __launch_bounds__(256)
void groupnorm_kernel(const float* __restrict__ x, const float* __restrict__ gamma,
                      const float* __restrict__ beta, ht* __restrict__ xn) {
    const int b = blockIdx.x >> 5, g = blockIdx.x & 31;
    const float* xp = x + (size_t)b * CHN + (size_t)g * (16 * NSP);

    float s = 0.f, s2 = 0.f;
    for (int i = threadIdx.x; i < 16 * NSP; i += 256) {
        float v = xp[i]; s += v; s2 += v * v;
    }
    __shared__ float rs[8], rs2[8];
    for (int o = 16; o; o >>= 1) {
        s  += __shfl_xor_sync(0xffffffffu, s,  o);
        s2 += __shfl_xor_sync(0xffffffffu, s2, o);
    }
    int wid = threadIdx.x >> 5;
    if ((threadIdx.x & 31) == 0) { rs[wid] = s; rs2[wid] = s2; }
    __syncthreads();
    s = 0.f; s2 = 0.f;
    #pragma unroll
    for (int i = 0; i < 8; i++) { s += rs[i]; s2 += rs2[i]; }
    const float inv = 1.0f / (16 * NSP);
    float mu = s * inv;
    float rstd = rsqrtf(s2 * inv - mu * mu + 1e-5f);

    const int gc = g * 16;
    for (int n = threadIdx.x; n < NSP; n += 256) {
        union { ht h[16]; uint4 u[2]; } H;
        #pragma unroll
        for (int c = 0; c < 16; ++c) {
            float v = (xp[c * NSP + n] - mu) * rstd * gamma[gc + c] + beta[gc + c];
            H.h[c] = __float2half_rn(v);
        }
        uint4* dh = (uint4*)(g_xn + (size_t)b * (NSP * NCH) + (size_t)n * NCH + gc);
        dh[0] = H.u[0]; dh[1] = H.u[1];
    }
}

// ------------------------------ Softmax --------------------------------------
__global__ __launch_bounds__(256)
void softmax_kernel(const float* __restrict__ S, ht* __restrict__ P) {
    const float4* row = (const float4*)(S + (size_t)blockIdx.x * NSP);
    int tid = threadIdx.x;
    float4 v = row[tid];
    __shared__ float red[8];

    float m = fmaxf(fmaxf(v.x, v.y), fmaxf(v.z, v.w));
    for (int o = 16; o; o >>= 1) m = fmaxf(m, __shfl_xor_sync(0xffffffffu, m, o));
    if ((tid & 31) == 0) red[tid >> 5] = m;
    __syncthreads();
    m = red[0];
    #pragma unroll
    for (int i = 1; i < 8; i++) m = fmaxf(m, red[i]);

    v.x = __expf(v.x - m); v.y = __expf(v.y - m);
    v.z = __expf(v.z - m); v.w = __expf(v.w - m);
    float s = v.x + v.y + v.z + v.w;
    for (int o = 16; o; o >>= 1) s += __shfl_xor_sync(0xffffffffu, s, o);
    __syncthreads();
    if ((tid & 31) == 0) red[tid >> 5] = s;
    __syncthreads();
    s = 0.f;
    #pragma unroll
    for (int i = 0; i < 8; i++) s += red[i];
    float inv = 1.0f / s;

    union { ht h[4]; uint2 u; } H;
    H.h[0] = __float2half_rn(v.x * inv); H.h[1] = __float2half_rn(v.y * inv);
    H.h[2] = __float2half_rn(v.z * inv); H.h[3] = __float2half_rn(v.w * inv);
    *(uint2*)(P + (size_t)blockIdx.x * NSP + tid * 4) = H.u;
}

// --------------------------- mma.sync GEMM -----------------------------------
// D[128x128] = A * B^T ; operands K-major fp16, single pass, 4-stage cp.async.
// MODE 0: QKV  (z=b)     M=1536 N=1024 K=512
// MODE 1: S    (z=b*4+h) M=1024 N=1024 K=128  -> fp32 S
// MODE 2: O    (z=b*4+h) M=128  N=1024 K=1024 -> oT fp16 (transposed)
// MODE 3: proj (z=b)     M=512  N=1024 K=512  -> fp32 out (+bias+x)
#define SROW   80          // padded row: 32 halfs + 16B pad
#define TILEB  10240       // 128 * 80
#define STAGEB 20480       // A + B tile
#define NSTAGE 4
#define SMEMSZ (NSTAGE*STAGEB)   // 81920

template<int MODE>
__global__ __launch_bounds__(256, 2)
void gemm_mma(const ht* __restrict__ Ap, const ht* __restrict__ Bp,
              float* __restrict__ C,
              ht* __restrict__ Oh, ht* __restrict__ Vh,
              const float* __restrict__ bias, const float* __restrict__ resid) {
    extern __shared__ char smem[];
    const uint32_t sbase = smem_u32(smem);
    const int tid = threadIdx.x, lane = tid & 31, wid = tid >> 5;
    const int wm = wid & 3, wn = wid >> 2;       // 4 warps M, 2 warps N
    const int m_w = wm * 32, n_w = wn * 64;
    const int z = blockIdx.z, m0 = blockIdx.y * 128, n0 = blockIdx.x * 128;

    int lda, ldb, Ktot;
    size_t aoff, boff;
    if (MODE == 0) {
        lda = 512; ldb = 512; Ktot = 512;
        aoff = (size_t)m0 * 512;
        boff = (size_t)z * (NSP * NCH) + (size_t)n0 * 512;
    } else if (MODE == 1) {
        lda = 1024; ldb = 1024; Ktot = 128;
        int b = z >> 2, h = z & 3;
        aoff = (size_t)b * (NSP * 1024) + (size_t)m0 * 1024 + h * 128;
        boff = (size_t)b * (NSP * 1024) + (size_t)n0 * 1024 + 512 + h * 128;
    } else if (MODE == 2) {
        lda = 1024; ldb = 1024; Ktot = 1024;
        int b = z >> 2, h = z & 3;
        aoff = (size_t)b * (NCH * NSP) + (size_t)(h * 128) * NSP;
        boff = (size_t)z * (size_t)NSNS + (size_t)n0 * 1024;
    } else {
        lda = 512; ldb = 512; Ktot = 512;
        aoff = (size_t)m0 * 512;
        boff = (size_t)z * (NSP * NCH) + (size_t)n0 * 512;
    }

    float acc[2][8][4] = {};
    const int NIT = Ktot / 32;

    // 1024 16B-chunks/stage (A 512 + B 512), 4 per thread
    int ct[4], cr[4], cc[4];
    #pragma unroll
    for (int i = 0; i < 4; ++i) {
        int c = tid + i * 256;
        ct[i] = c >> 9; cr[i] = (c >> 2) & 127; cc[i] = c & 3;
    }

    auto load_stage = [&](int it, int s) {
        const int k0 = it * 32;
        const uint32_t sb = sbase + s * STAGEB;
        #pragma unroll
        for (int i = 0; i < 4; ++i) {
            const ht* gp = (ct[i] == 0)
                ? Ap + aoff + (size_t)cr[i] * lda + k0 + cc[i] * 8
                : Bp + boff + (size_t)cr[i] * ldb + k0 + cc[i] * 8;
            CP_ASYNC(sb + ct[i] * TILEB + cr[i] * SROW + cc[i] * 16, gp);
        }
        CP_COMMIT();
    };

    #pragma unroll
    for (int p = 0; p < NSTAGE - 1; ++p)
        if (p < NIT) load_stage(p, p);

    for (int it = 0; it < NIT; ++it) {
        const int s = it & (NSTAGE - 1);
        if (it + NSTAGE - 1 < NIT) {
            load_stage(it + NSTAGE - 1, (it + NSTAGE - 1) & (NSTAGE - 1));
            CP_WAIT3();
        } else {
            CP_WAIT0();
        }
        __syncthreads();

        const uint32_t ab = sbase + s * STAGEB;
        const uint32_t rofs = (lane & 15) * SROW + ((lane >> 4) << 4);
        #pragma unroll
        for (int k16 = 0; k16 < 2; ++k16) {
            const uint32_t ko = k16 * 32 + rofs;
            uint32_t bfr[4][4];
            #pragma unroll
            for (int j = 0; j < 4; ++j)
                ldsm4(bfr[j], ab + TILEB + (n_w + j * 16) * SROW + ko);
            uint32_t af[2][4];
            #pragma unroll
            for (int i = 0; i < 2; ++i)
                ldsm4(af[i], ab + (m_w + i * 16) * SROW + ko);
            #pragma unroll
            for (int i = 0; i < 2; ++i)
                #pragma unroll
                for (int jn = 0; jn < 8; ++jn)
                    mma16816(acc[i][jn], af[i],
                             bfr[jn >> 1][jn & 1], bfr[jn >> 1][(jn & 1) + 2]);
        }
        __syncthreads();
    }

    // ------------------------------ epilogue ---------------------------------
    const int fr = lane >> 2;            // frag row 0..7
    const int fc = (lane & 3) * 2;       // frag col (even)

    if (MODE == 1 || MODE == 3) {
        #pragma unroll
        for (int i = 0; i < 2; ++i)
            #pragma unroll
            for (int jn = 0; jn < 8; ++jn)
                #pragma unroll
                for (int rh = 0; rh < 2; ++rh) {
                    int row = m0 + m_w + i * 16 + fr + rh * 8;
                    int col = n0 + n_w + jn * 8 + fc;
                    float v0 = acc[i][jn][rh * 2], v1 = acc[i][jn][rh * 2 + 1];
                    if (MODE == 3) {
                        float bv = bias[row];
                        const float2 xv = *(const float2*)(resid + (size_t)z * CHN + (size_t)row * NSP + col);
                        *(float2*)(C + (size_t)z * CHN + (size_t)row * NSP + col) =
                            make_float2(v0 + bv + xv.x, v1 + bv + xv.y);
                    } else {
                        *(float2*)(C + (size_t)z * NSNS + (size_t)row * NSP + col) =
                            make_float2(v0, v1);
                    }
                }
    } else if (MODE == 0 && m0 >= 1024) {
        // V region: direct [b][c][m]
        #pragma unroll
        for (int i = 0; i < 2; ++i)
            #pragma unroll
            for (int jn = 0; jn < 8; ++jn)
                #pragma unroll
                for (int rh = 0; rh < 2; ++rh) {
                    int mi = m_w + i * 16 + fr + rh * 8;
                    float bv = bias[m0 + mi];
                    int cc2 = m0 - 1024 + mi;
                    size_t off = (size_t)z * (NCH * NSP) + (size_t)cc2 * NSP + n0 + n_w + jn * 8 + fc;
                    *(__half2*)(Vh + off) = __halves2half2(
                        __float2half_rn(acc[i][jn][rh * 2] + bv),
                        __float2half_rn(acc[i][jn][rh * 2 + 1] + bv));
                }
    } else {
        // transpose path: MODE 0 q/k region, MODE 2 oT
        uint32_t* TB = (uint32_t*)smem;       // [64 n][132 m]
        #pragma unroll
        for (int hh = 0; hh < 2; ++hh) {
            __syncthreads();
            if (wn == hh) {
                #pragma unroll
                for (int i = 0; i < 2; ++i)
                    #pragma unroll
                    for (int jn = 0; jn < 8; ++jn)
                        #pragma unroll
                        for (int rh = 0; rh < 2; ++rh) {
                            int mi = m_w + i * 16 + fr + rh * 8;
                            float bv = 0.f;
                            if (MODE == 0) {
                                bv = bias[m0 + mi];
                                if (m0 < 512) bv *= QS;
                            }
                            float v0 = acc[i][jn][rh * 2] + bv;
                            float v1 = acc[i][jn][rh * 2 + 1] + bv;
                            int ncl = jn * 8 + fc;
                            TB[ncl * 132 + mi]       = (uint32_t)__half_as_ushort(__float2half_rn(v0));
                            TB[(ncl + 1) * 132 + mi] = (uint32_t)__half_as_ushort(__float2half_rn(v1));
                        }
            }
            __syncthreads();
            int rr = tid >> 2, seg = (tid & 3) * 32;
            size_t nco;
            if (MODE == 0) {
                nco = (size_t)z * (NSP * 1024) + (size_t)(n0 + hh * 64 + rr) * 1024 + m0 + seg;
            } else {
                int b = z >> 2, h = z & 3;
                nco = (size_t)b * (NSP * NCH) + (size_t)(n0 + hh * 64 + rr) * NCH + h * 128 + seg;
            }
            #pragma unroll
            for (int q4 = 0; q4 < 4; ++q4) {
                union { ht h[8]; uint4 u; } H;
                #pragma unroll
                for (int e = 0; e < 8; ++e)
                    H.h[e] = __ushort_as_half((unsigned short)(TB[rr * 132 + seg + q4 * 8 + e] & 0xffffu));
                *(uint4*)(Oh + nco + q4 * 8) = H.u;
            }
        }
    }
}

// ------------------------------ launch ---------------------------------------
extern "C" void kernel_launch(void* const* d_in, const int* in_sizes, int n_in,
                              void* d_out, int out_size) {
    const float* x      = (const float*)d_in[0];
    const float* gamma  = (const float*)d_in[1];
    const float* beta   = (const float*)d_in[2];
    const float* w_qkv  = (const float*)d_in[3];
    const float* b_qkv  = (const float*)d_in[4];
    const float* w_proj = (const float*)d_in[5];
    const float* b_proj = (const float*)d_in[6];
    float* out = (float*)d_out;

    ht *xn, *wq, *wp, *qk, *v, *P, *oT;
    float* S;
    cudaGetSymbolAddress((void**)&xn, g_xn);
    cudaGetSymbolAddress((void**)&wq, g_wq);
    cudaGetSymbolAddress((void**)&wp, g_wp);
    cudaGetSymbolAddress((void**)&qk, g_qk);
    cudaGetSymbolAddress((void**)&v,  g_v);
    cudaGetSymbolAddress((void**)&S,  g_S);
    cudaGetSymbolAddress((void**)&P,  g_P);
    cudaGetSymbolAddress((void**)&oT, g_oT);

    cudaFuncSetAttribute(gemm_mma<0>, cudaFuncAttributeMaxDynamicSharedMemorySize, SMEMSZ);
    cudaFuncSetAttribute(gemm_mma<1>, cudaFuncAttributeMaxDynamicSharedMemorySize, SMEMSZ);
    cudaFuncSetAttribute(gemm_mma<2>, cudaFuncAttributeMaxDynamicSharedMemorySize, SMEMSZ);
    cudaFuncSetAttribute(gemm_mma<3>, cudaFuncAttributeMaxDynamicSharedMemorySize, SMEMSZ);

    convw_kernel<<<4096, 256>>>(w_qkv, w_proj, wq, wp);
    groupnorm_kernel<<<NB * 32, 256>>>(x, gamma, beta, xn);

    // QKV: q/k -> qkT (transposed), v -> [b][c][m]
    gemm_mma<0><<<dim3(8, 12, NB), 256, SMEMSZ>>>(
        wq, xn, nullptr, qk, v, b_qkv, nullptr);
    // S = (q*scale)^T k
    gemm_mma<1><<<dim3(8, 8, 64), 256, SMEMSZ>>>(
        qk, qk, S, nullptr, nullptr, nullptr, nullptr);
    // softmax -> P fp16
    softmax_kernel<<<64 * NSP, 256>>>(S, P);
    // O = V P^T -> oT
    gemm_mma<2><<<dim3(8, 1, 64), 256, SMEMSZ>>>(
        v, P, nullptr, oT, nullptr, nullptr, nullptr);
    // out = x + w_proj O + b_proj
    gemm_mma<3><<<dim3(8, 4, NB), 256, SMEMSZ>>>(
        wp, oT, out, nullptr, nullptr, b_proj, x);
}